// round 11
// baseline (speedup 1.0000x reference)
#include <cuda_runtime.h>
#include <cstdint>
#include <cstddef>

#define NUM_VARS  512
#define EMBED_DIM 32
#define IN_DIM    512
#define TOP_K     10
#define BATCH     256
#define TI        16                       // rows per tile
#define NITEMS    (BATCH * (NUM_VARS/TI))  // 8192 work items
#define GRID      304

// vbuf layout: row stride = 32 lanes * 20 words (16 used + 4 pad) = 640 words
#define VROW_STRIDE 640
#define LANE_STRIDE 20

// scratch (no allocations allowed)
__device__ float g_s[BATCH * EMBED_DIM];   // (c*c)[b][e]
__device__ float g_gate[BATCH];            // sigmoid(c@Wg+bg)

// order-preserving float->u32 key: key(a) > key(b)  <=>  a > b (finite floats)
__device__ __forceinline__ unsigned f2key(float f) {
    const unsigned u = __float_as_uint(f);
    return u ^ ((unsigned)((int)u >> 31) | 0x80000000u);
}
__device__ __forceinline__ float key2f(unsigned k) {
    const unsigned u = k ^ ((unsigned)((int)(~k) >> 31) | 0x80000000u);
    return __uint_as_float(u);
}

// --------------------------------------------------------------------------
// Kernel A: context MLP -> c, s=c^2, gate. One block per batch row.
// --------------------------------------------------------------------------
__global__ __launch_bounds__(128) void ctx_kernel(
    const float* __restrict__ x,    // [B, 512]
    const float* __restrict__ W1,   // [32, 512]
    const float* __restrict__ b1,   // [32]
    const float* __restrict__ W2,   // [32, 32]
    const float* __restrict__ b2,   // [32]
    const float* __restrict__ Wg,   // [32]
    const float* __restrict__ bg)   // [1]
{
    __shared__ float xs[IN_DIM];
    __shared__ float hs[EMBED_DIM];
    const int b   = blockIdx.x;
    const int tid = threadIdx.x;
    const float* xrow = x + (size_t)b * IN_DIM;
    for (int i = tid; i < IN_DIM; i += 128) xs[i] = xrow[i];
    __syncthreads();

    const int w = tid >> 5, l = tid & 31;
    for (int eo = 0; eo < 8; ++eo) {
        const int e = w * 8 + eo;
        const float* wrow = W1 + (size_t)e * IN_DIM;
        float p = 0.f;
        #pragma unroll 4
        for (int k = l; k < IN_DIM; k += 32) p = fmaf(xs[k], wrow[k], p);
        #pragma unroll
        for (int o = 16; o; o >>= 1) p += __shfl_xor_sync(0xffffffffu, p, o);
        if (l == 0) hs[e] = fmaxf(p + b1[e], 0.f);
    }
    __syncthreads();

    if (w == 0) {
        const int e = l;
        float c = b2[e];
        #pragma unroll
        for (int k = 0; k < EMBED_DIM; ++k) c = fmaf(W2[e * EMBED_DIM + k], hs[k], c);
        g_s[b * EMBED_DIM + e] = c * c;
        float gp = c * Wg[e];
        #pragma unroll
        for (int o = 16; o; o >>= 1) gp += __shfl_xor_sync(0xffffffffu, gp, o);
        if (e == 0) g_gate[b] = __fdividef(1.f, 1.f + __expf(-(gp + bg[0])));
    }
}

// --------------------------------------------------------------------------
// Kernel B: persistent adj (raw logits) + key top-k + winner-only sigmoid.
// smem: ebuf4 [8 ef][512 j] float4 (64 KB)
//       vbuf  [16 rows][640] u32 keys (40 KB, lane-contiguous, pad 20)
//       abuf  [16 rows][16 ep] float2 (2 KB)
// --------------------------------------------------------------------------
#define SMEM_EBUF_BYTES (8 * NUM_VARS * 16)
#define SMEM_VBUF_BYTES (TI * VROW_STRIDE * 4)
#define SMEM_ABUF_BYTES (TI * 16 * 8)
#define SMEM_TOTAL (SMEM_EBUF_BYTES + SMEM_VBUF_BYTES + SMEM_ABUF_BYTES)

// local top-2 over the lane's 16 owned key slots; strict '>' keeps the
// smallest index on exact key ties (key ties <=> logit ties), matching jax.
__device__ __forceinline__ void scan_top2(const unsigned* __restrict__ lptr, int base,
                                          unsigned& t1, int& i1,
                                          unsigned& t2, int& i2) {
    t1 = 0u; i1 = base; t2 = 0u; i2 = base;
    #pragma unroll
    for (int cc = 0; cc < 4; ++cc) {
        const uint4 vv = reinterpret_cast<const uint4*>(lptr)[cc];
        const unsigned va[4] = {vv.x, vv.y, vv.z, vv.w};
        #pragma unroll
        for (int u = 0; u < 4; ++u) {
            const unsigned bx = va[u];
            const int j = base + 4 * cc + u;
            const bool p1 = bx > t1;
            const bool p2 = bx > t2;
            t2 = p1 ? t1 : (p2 ? bx : t2);
            i2 = p1 ? i1 : (p2 ? j  : i2);
            t1 = p1 ? bx : t1;
            i1 = p1 ? j  : i1;
        }
    }
}

__global__ __launch_bounds__(256, 2) void adj_kernel(
    const float* __restrict__ emb,   // [512, 32]
    float* __restrict__ out)         // [256, 512, 512]
{
    extern __shared__ unsigned char smem_raw[];
    float4*   ebuf4 = reinterpret_cast<float4*>(smem_raw);
    unsigned* vbuf  = reinterpret_cast<unsigned*>(smem_raw + SMEM_EBUF_BYTES);
    float2*   abuf2 = reinterpret_cast<float2*>(smem_raw + SMEM_EBUF_BYTES + SMEM_VBUF_BYTES);
    ulonglong2* ebufU2 = reinterpret_cast<ulonglong2*>(ebuf4);
    ulonglong2* abufU2 = reinterpret_cast<ulonglong2*>(abuf2);

    const int tid = threadIdx.x;

    // Stage emb once: ebuf4[ef][j] = emb[j][4ef..4ef+3]
    for (int idx = tid; idx < NUM_VARS * 8; idx += 256) {
        const int j = idx >> 3, ef = idx & 7;
        ebuf4[ef * NUM_VARS + j] = reinterpret_cast<const float4*>(emb)[idx];
    }
    __syncthreads();

    const int tj = tid & 63;     // column group (j = tj + 64q)
    const int ti = tid >> 6;     // row group   (i = ti*4 + k)
    const int w  = tid >> 5, l = tid & 31;
    const int tjoff = ((tj >> 4) * LANE_STRIDE) + (tj & 15);  // vbuf col offset

    for (int item = blockIdx.x; item < NITEMS; item += GRID) {
        const int b  = item >> 5;
        const int i0 = (item & 31) * TI;

        // abuf[i][ep] = emb[i0+i][2ep..2ep+1] * s[b][2ep..2ep+1]
        {
            const int i = tid >> 4, ep = tid & 15;
            float2 ev = reinterpret_cast<const float2*>(emb)[(i0 + i) * 16 + ep];
            float2 sv = reinterpret_cast<const float2*>(g_s + b * EMBED_DIM)[ep];
            ev.x *= sv.x; ev.y *= sv.y;
            abuf2[i * 16 + ep] = ev;
        }
        __syncthreads();

        // ---- main f32x2 FMA loop: 4 rows x 8 cols, float4 (2 e-pairs) steps ----
        unsigned long long acc[4][8];
        #pragma unroll
        for (int i = 0; i < 4; ++i)
            #pragma unroll
            for (int q = 0; q < 8; ++q) acc[i][q] = 0ull;

        #pragma unroll
        for (int ef = 0; ef < 8; ++ef) {
            ulonglong2 av[4];
            #pragma unroll
            for (int i = 0; i < 4; ++i) av[i] = abufU2[(ti * 4 + i) * 8 + ef]; // broadcast
            #pragma unroll
            for (int q = 0; q < 8; ++q) {
                const ulonglong2 bv = ebufU2[ef * NUM_VARS + tj + 64 * q];
                #pragma unroll
                for (int i = 0; i < 4; ++i) {
                    asm("fma.rn.f32x2 %0, %1, %2, %0;"
                        : "+l"(acc[i][q]) : "l"(av[i].x), "l"(bv.x));
                    asm("fma.rn.f32x2 %0, %1, %2, %0;"
                        : "+l"(acc[i][q]) : "l"(av[i].y), "l"(bv.y));
                }
            }
        }

        // ---- zero both output rows now (STG latency overlaps epilogue ALU;
        //      post-epilogue __syncthreads orders these before winner stores) ----
        float* rowa = out + ((size_t)b * NUM_VARS + (i0 + 2 * w)) * NUM_VARS;
        float* rowb = rowa + NUM_VARS;
        {
            const float4 z = make_float4(0.f, 0.f, 0.f, 0.f);
            #pragma unroll
            for (int c = 0; c < 4; ++c) {
                reinterpret_cast<float4*>(rowa)[c * 32 + l] = z;
                reinterpret_cast<float4*>(rowb)[c * 32 + l] = z;
            }
        }

        // ---- key epilogue -> vbuf (no sigmoid here: monotone => same top-k) ----
        #pragma unroll
        for (int i = 0; i < 4; ++i) {
            #pragma unroll
            for (int q = 0; q < 8; ++q) {
                const float lo = __uint_as_float((unsigned)acc[i][q]);
                const float hi = __uint_as_float((unsigned)(acc[i][q] >> 32));
                vbuf[(ti * 4 + i) * VROW_STRIDE + q * (4 * LANE_STRIDE) + tjoff]
                    = f2key(lo + hi);
            }
        }
        __syncthreads();

        const float gate = g_gate[b];

        // ---- exact top-10 on keys: warp w owns rows 2w, 2w+1, interleaved ----
        {
            const unsigned* lpa = vbuf + (2 * w) * VROW_STRIDE + l * LANE_STRIDE;
            const unsigned* lpb = lpa + VROW_STRIDE;
            const int base = l * 16;

            unsigned t1a, t2a, t1b, t2b; int i1a, i2a, i1b, i2b;
            scan_top2(lpa, base, t1a, i1a, t2a, i2a);
            scan_top2(lpb, base, t1b, i1b, t2b, i2b);
            bool h2a = true, h2b = true;

            #pragma unroll 1
            for (int it = 0; it < TOP_K; ++it) {
                unsigned wm0, wm1;
                asm("redux.sync.max.u32 %0, %1, 0xffffffff;" : "=r"(wm0) : "r"(t1a));
                asm("redux.sync.max.u32 %0, %1, 0xffffffff;" : "=r"(wm1) : "r"(t1b));
                const unsigned ba = __ballot_sync(0xffffffffu, t1a == wm0);
                const unsigned bb = __ballot_sync(0xffffffffu, t1b == wm1);
                if (l == __ffs(ba) - 1) {            // min index on ties
                    const float logit = key2f(wm0);
                    rowa[i1a] = __fdividef(gate, 1.f + __expf(-logit));
                    *(unsigned*)(lpa + (i1a & 15)) = 0u;   // remove (key 0 < all)
                    if (it < TOP_K - 1) {
                        if (h2a) { t1a = t2a; i1a = i2a; h2a = false; }
                        else     { scan_top2(lpa, base, t1a, i1a, t2a, i2a); h2a = true; }
                    }
                }
                if (l == __ffs(bb) - 1) {
                    const float logit = key2f(wm1);
                    rowb[i1b] = __fdividef(gate, 1.f + __expf(-logit));
                    *(unsigned*)(lpb + (i1b & 15)) = 0u;
                    if (it < TOP_K - 1) {
                        if (h2b) { t1b = t2b; i1b = i2b; h2b = false; }
                        else     { scan_top2(lpb, base, t1b, i1b, t2b, i2b); h2b = true; }
                    }
                }
                // no __syncwarp needed: lanes touch only their own vbuf slots;
                // redux/ballot reconverge the warp each iteration.
            }
        }
        __syncthreads();   // vbuf/abuf reuse barrier
    }
}

// --------------------------------------------------------------------------
extern "C" void kernel_launch(void* const* d_in, const int* in_sizes, int n_in,
                              void* d_out, int out_size) {
    const float* ctx = (const float*)d_in[0];  // [256,512]
    const float* emb = (const float*)d_in[1];  // [512,32]
    const float* W1  = (const float*)d_in[2];  // [32,512]
    const float* b1  = (const float*)d_in[3];  // [32]
    const float* W2  = (const float*)d_in[4];  // [32,32]
    const float* b2  = (const float*)d_in[5];  // [32]
    const float* Wg  = (const float*)d_in[6];  // [1,32]
    const float* bg  = (const float*)d_in[7];  // [1]
    float* out = (float*)d_out;

    ctx_kernel<<<BATCH, 128>>>(ctx, W1, b1, W2, b2, Wg, bg);

    cudaFuncSetAttribute(adj_kernel,
                         cudaFuncAttributeMaxDynamicSharedMemorySize, SMEM_TOTAL);
    adj_kernel<<<GRID, 256, SMEM_TOTAL>>>(emb, out);
}

// round 12
// speedup vs baseline: 1.0328x; 1.0328x over previous
#include <cuda_runtime.h>
#include <cstdint>
#include <cstddef>

#define NUM_VARS  512
#define EMBED_DIM 32
#define IN_DIM    512
#define TOP_K     10
#define BATCH     256
#define TI        16                       // rows per tile
#define NITEMS    (BATCH * (NUM_VARS/TI))  // 8192 work items
#define GRID      304

// vbuf layout: row stride = 32 lanes * 20 words (16 used + 4 pad) = 640 floats
#define VROW_STRIDE 640
#define LANE_STRIDE 20

// scratch (no allocations allowed)
__device__ float g_s[BATCH * EMBED_DIM];   // (c*c)[b][e]
__device__ float g_gate[BATCH];            // sigmoid(c@Wg+bg)

// --------------------------------------------------------------------------
// Kernel A: context MLP -> c, s=c^2, gate. One block per batch row.
// Signals programmatic completion so the dependent adj_kernel can launch
// early and overlap its ctx-independent prologue with this kernel.
// --------------------------------------------------------------------------
__global__ __launch_bounds__(128) void ctx_kernel(
    const float* __restrict__ x,    // [B, 512]
    const float* __restrict__ W1,   // [32, 512]
    const float* __restrict__ b1,   // [32]
    const float* __restrict__ W2,   // [32, 32]
    const float* __restrict__ b2,   // [32]
    const float* __restrict__ Wg,   // [32]
    const float* __restrict__ bg)   // [1]
{
    __shared__ float xs[IN_DIM];
    __shared__ float hs[EMBED_DIM];
    const int b   = blockIdx.x;
    const int tid = threadIdx.x;
    const float* xrow = x + (size_t)b * IN_DIM;
    for (int i = tid; i < IN_DIM; i += 128) xs[i] = xrow[i];
    __syncthreads();

    const int w = tid >> 5, l = tid & 31;
    for (int eo = 0; eo < 8; ++eo) {
        const int e = w * 8 + eo;
        const float* wrow = W1 + (size_t)e * IN_DIM;
        float p = 0.f;
        #pragma unroll 4
        for (int k = l; k < IN_DIM; k += 32) p = fmaf(xs[k], wrow[k], p);
        #pragma unroll
        for (int o = 16; o; o >>= 1) p += __shfl_xor_sync(0xffffffffu, p, o);
        if (l == 0) hs[e] = fmaxf(p + b1[e], 0.f);
    }
    __syncthreads();

    if (w == 0) {
        const int e = l;
        float c = b2[e];
        #pragma unroll
        for (int k = 0; k < EMBED_DIM; ++k) c = fmaf(W2[e * EMBED_DIM + k], hs[k], c);
        g_s[b * EMBED_DIM + e] = c * c;
        float gp = c * Wg[e];
        #pragma unroll
        for (int o = 16; o; o >>= 1) gp += __shfl_xor_sync(0xffffffffu, gp, o);
        if (e == 0) g_gate[b] = __fdividef(1.f, 1.f + __expf(-(gp + bg[0])));
    }
    // allow the dependent adj_kernel grid to begin launching
    cudaTriggerProgrammaticLaunchCompletion();
}

// --------------------------------------------------------------------------
// Kernel B: persistent adj + sigmoid + exact top-k + gated write.
// smem: ebuf4 [8 ef][512 j] float4 (64 KB)
//       vbuf  [16 rows][640] f32   (40 KB, lane-contiguous, pad 20)
//       abuf  [16 rows][16 ep] float2 (2 KB)
// --------------------------------------------------------------------------
#define SMEM_EBUF_BYTES (8 * NUM_VARS * 16)
#define SMEM_VBUF_BYTES (TI * VROW_STRIDE * 4)
#define SMEM_ABUF_BYTES (TI * 16 * 8)
#define SMEM_TOTAL (SMEM_EBUF_BYTES + SMEM_VBUF_BYTES + SMEM_ABUF_BYTES)

// local top-2 over the lane's 16 owned slots (u32-bit order == float order for
// sigmoid>0); strict '>' keeps the smallest index on ties, matching jax top_k.
__device__ __forceinline__ void scan_top2(const float* __restrict__ lptr, int base,
                                          unsigned& t1, int& i1,
                                          unsigned& t2, int& i2) {
    t1 = 0u; i1 = base; t2 = 0u; i2 = base;
    #pragma unroll
    for (int cc = 0; cc < 4; ++cc) {
        const float4 vv = reinterpret_cast<const float4*>(lptr)[cc];
        const float va[4] = {vv.x, vv.y, vv.z, vv.w};
        #pragma unroll
        for (int u = 0; u < 4; ++u) {
            const unsigned bx = __float_as_uint(va[u]);
            const int j = base + 4 * cc + u;
            const bool p1 = bx > t1;
            const bool p2 = bx > t2;
            t2 = p1 ? t1 : (p2 ? bx : t2);
            i2 = p1 ? i1 : (p2 ? j  : i2);
            t1 = p1 ? bx : t1;
            i1 = p1 ? j  : i1;
        }
    }
}

__global__ __launch_bounds__(256, 2) void adj_kernel(
    const float* __restrict__ emb,   // [512, 32]
    float* __restrict__ out)         // [256, 512, 512]
{
    extern __shared__ unsigned char smem_raw[];
    float4* ebuf4 = reinterpret_cast<float4*>(smem_raw);
    float*  vbuf  = reinterpret_cast<float*>(smem_raw + SMEM_EBUF_BYTES);
    float2* abuf2 = reinterpret_cast<float2*>(smem_raw + SMEM_EBUF_BYTES + SMEM_VBUF_BYTES);
    ulonglong2* ebufU2 = reinterpret_cast<ulonglong2*>(ebuf4);
    ulonglong2* abufU2 = reinterpret_cast<ulonglong2*>(abuf2);

    const int tid = threadIdx.x;

    // ---- ctx-independent prologue (overlaps ctx_kernel under PDL) ----
    // Stage emb once: ebuf4[ef][j] = emb[j][4ef..4ef+3]
    for (int idx = tid; idx < NUM_VARS * 8; idx += 256) {
        const int j = idx >> 3, ef = idx & 7;
        ebuf4[ef * NUM_VARS + j] = reinterpret_cast<const float4*>(emb)[idx];
    }

    // wait for ctx_kernel's g_s / g_gate to be complete & visible
    cudaGridDependencySynchronize();
    __syncthreads();

    const int tj = tid & 63;     // column group (j = tj + 64q)
    const int ti = tid >> 6;     // row group   (i = ti*4 + k)
    const int w  = tid >> 5, l = tid & 31;
    const int tjoff = ((tj >> 4) * LANE_STRIDE) + (tj & 15);  // vbuf col offset

    for (int item = blockIdx.x; item < NITEMS; item += GRID) {
        const int b  = item >> 5;
        const int i0 = (item & 31) * TI;

        // abuf[i][ep] = emb[i0+i][2ep..2ep+1] * s[b][2ep..2ep+1]
        {
            const int i = tid >> 4, ep = tid & 15;
            float2 ev = reinterpret_cast<const float2*>(emb)[(i0 + i) * 16 + ep];
            float2 sv = reinterpret_cast<const float2*>(g_s + b * EMBED_DIM)[ep];
            ev.x *= sv.x; ev.y *= sv.y;
            abuf2[i * 16 + ep] = ev;
        }
        __syncthreads();

        // ---- main f32x2 FMA loop: 4 rows x 8 cols, float4 (2 e-pairs) steps ----
        unsigned long long acc[4][8];
        #pragma unroll
        for (int i = 0; i < 4; ++i)
            #pragma unroll
            for (int q = 0; q < 8; ++q) acc[i][q] = 0ull;

        #pragma unroll
        for (int ef = 0; ef < 8; ++ef) {
            ulonglong2 av[4];
            #pragma unroll
            for (int i = 0; i < 4; ++i) av[i] = abufU2[(ti * 4 + i) * 8 + ef]; // broadcast
            #pragma unroll
            for (int q = 0; q < 8; ++q) {
                const ulonglong2 bv = ebufU2[ef * NUM_VARS + tj + 64 * q];
                #pragma unroll
                for (int i = 0; i < 4; ++i) {
                    asm("fma.rn.f32x2 %0, %1, %2, %0;"
                        : "+l"(acc[i][q]) : "l"(av[i].x), "l"(bv.x));
                    asm("fma.rn.f32x2 %0, %1, %2, %0;"
                        : "+l"(acc[i][q]) : "l"(av[i].y), "l"(bv.y));
                }
            }
        }

        const float gate = g_gate[b];

        // ---- sigmoid epilogue -> vbuf (lane-contiguous layout) ----
        #pragma unroll
        for (int i = 0; i < 4; ++i) {
            #pragma unroll
            for (int q = 0; q < 8; ++q) {
                const float lo = __uint_as_float((unsigned)acc[i][q]);
                const float hi = __uint_as_float((unsigned)(acc[i][q] >> 32));
                const float xv = lo + hi;
                const float v  = __fdividef(1.f, 1.f + __expf(-xv));
                vbuf[(ti * 4 + i) * VROW_STRIDE + q * (4 * LANE_STRIDE) + tjoff] = v;
            }
        }
        __syncthreads();

        // ---- exact top-10: warp w owns rows 2w, 2w+1, interleaved ----
        {
            const int ra = 2 * w, rb = 2 * w + 1;
            float* rowa = out + ((size_t)b * NUM_VARS + (i0 + ra)) * NUM_VARS;
            float* rowb = rowa + NUM_VARS;
            const float* lpa = vbuf + ra * VROW_STRIDE + l * LANE_STRIDE;
            const float* lpb = lpa + VROW_STRIDE;
            const int base = l * 16;

            // zero both output rows (coalesced float4)
            const float4 z = make_float4(0.f, 0.f, 0.f, 0.f);
            #pragma unroll
            for (int c = 0; c < 4; ++c) {
                reinterpret_cast<float4*>(rowa)[c * 32 + l] = z;
                reinterpret_cast<float4*>(rowb)[c * 32 + l] = z;
            }

            unsigned t1a, t2a, t1b, t2b; int i1a, i2a, i1b, i2b;
            scan_top2(lpa, base, t1a, i1a, t2a, i2a);
            scan_top2(lpb, base, t1b, i1b, t2b, i2b);
            bool h2a = true, h2b = true;
            __syncwarp();   // order zero-stores before winner stores

            #pragma unroll 1
            for (int it = 0; it < TOP_K; ++it) {
                unsigned wm0, wm1;
                asm("redux.sync.max.u32 %0, %1, 0xffffffff;" : "=r"(wm0) : "r"(t1a));
                asm("redux.sync.max.u32 %0, %1, 0xffffffff;" : "=r"(wm1) : "r"(t1b));
                const unsigned ba = __ballot_sync(0xffffffffu, t1a == wm0);
                const unsigned bb = __ballot_sync(0xffffffffu, t1b == wm1);
                if (l == __ffs(ba) - 1) {            // min index on ties
                    rowa[i1a] = __uint_as_float(wm0) * gate;
                    *(float*)(lpa + (i1a & 15)) = 0.f;   // remove (bits 0)
                    if (it < TOP_K - 1) {
                        if (h2a) { t1a = t2a; i1a = i2a; h2a = false; }
                        else     { scan_top2(lpa, base, t1a, i1a, t2a, i2a); h2a = true; }
                    }
                }
                if (l == __ffs(bb) - 1) {
                    rowb[i1b] = __uint_as_float(wm1) * gate;
                    *(float*)(lpb + (i1b & 15)) = 0.f;
                    if (it < TOP_K - 1) {
                        if (h2b) { t1b = t2b; i1b = i2b; h2b = false; }
                        else     { scan_top2(lpb, base, t1b, i1b, t2b, i2b); h2b = true; }
                    }
                }
                // no __syncwarp needed: lanes touch only their own vbuf slots;
                // redux/ballot reconverge the warp each iteration.
            }
        }
        __syncthreads();   // vbuf/abuf reuse barrier
    }
}

// --------------------------------------------------------------------------
extern "C" void kernel_launch(void* const* d_in, const int* in_sizes, int n_in,
                              void* d_out, int out_size) {
    const float* ctx = (const float*)d_in[0];  // [256,512]
    const float* emb = (const float*)d_in[1];  // [512,32]
    const float* W1  = (const float*)d_in[2];  // [32,512]
    const float* b1  = (const float*)d_in[3];  // [32]
    const float* W2  = (const float*)d_in[4];  // [32,32]
    const float* b2  = (const float*)d_in[5];  // [32]
    const float* Wg  = (const float*)d_in[6];  // [1,32]
    const float* bg  = (const float*)d_in[7];  // [1]
    float* out = (float*)d_out;

    ctx_kernel<<<BATCH, 128>>>(ctx, W1, b1, W2, b2, Wg, bg);

    cudaFuncSetAttribute(adj_kernel,
                         cudaFuncAttributeMaxDynamicSharedMemorySize, SMEM_TOTAL);

    // PDL launch: adj may begin (staging emb) while ctx is still running;
    // cudaGridDependencySynchronize() inside adj gates the g_s/g_gate reads.
    cudaLaunchConfig_t cfg = {};
    cfg.gridDim  = dim3(GRID, 1, 1);
    cfg.blockDim = dim3(256, 1, 1);
    cfg.dynamicSmemBytes = SMEM_TOTAL;
    cfg.stream = 0;
    cudaLaunchAttribute attr[1];
    attr[0].id = cudaLaunchAttributeProgrammaticStreamSerialization;
    attr[0].val.programmaticStreamSerializationAllowed = 1;
    cfg.attrs = attr;
    cfg.numAttrs = 1;
    cudaLaunchKernelEx(&cfg, adj_kernel, emb, out);
}

// round 13
// speedup vs baseline: 1.0659x; 1.0320x over previous
#include <cuda_runtime.h>
#include <cstdint>
#include <cstddef>

#define NUM_VARS  512
#define EMBED_DIM 32
#define IN_DIM    512
#define TOP_K     10
#define BATCH     256
#define TI        16                       // rows per tile
#define NITEMS    (BATCH * (NUM_VARS/TI))  // 8192 work items
#define GRID      304

// vbuf layout: row stride = 32 lanes * 20 words (16 used + 4 pad) = 640 floats
#define VROW_STRIDE 640
#define LANE_STRIDE 20

// scratch (no allocations allowed)
__device__ float g_s[BATCH * EMBED_DIM];   // (c*c)[b][e]
__device__ float g_gate[BATCH];            // sigmoid(c@Wg+bg)

// --------------------------------------------------------------------------
// Kernel A: context MLP -> c, s=c^2, gate. One block per batch row.
// --------------------------------------------------------------------------
__global__ __launch_bounds__(128) void ctx_kernel(
    const float* __restrict__ x,    // [B, 512]
    const float* __restrict__ W1,   // [32, 512]
    const float* __restrict__ b1,   // [32]
    const float* __restrict__ W2,   // [32, 32]
    const float* __restrict__ b2,   // [32]
    const float* __restrict__ Wg,   // [32]
    const float* __restrict__ bg)   // [1]
{
    __shared__ float xs[IN_DIM];
    __shared__ float hs[EMBED_DIM];
    const int b   = blockIdx.x;
    const int tid = threadIdx.x;
    const float* xrow = x + (size_t)b * IN_DIM;
    for (int i = tid; i < IN_DIM; i += 128) xs[i] = xrow[i];
    __syncthreads();

    const int w = tid >> 5, l = tid & 31;
    for (int eo = 0; eo < 8; ++eo) {
        const int e = w * 8 + eo;
        const float* wrow = W1 + (size_t)e * IN_DIM;
        float p = 0.f;
        #pragma unroll 4
        for (int k = l; k < IN_DIM; k += 32) p = fmaf(xs[k], wrow[k], p);
        #pragma unroll
        for (int o = 16; o; o >>= 1) p += __shfl_xor_sync(0xffffffffu, p, o);
        if (l == 0) hs[e] = fmaxf(p + b1[e], 0.f);
    }
    __syncthreads();

    if (w == 0) {
        const int e = l;
        float c = b2[e];
        #pragma unroll
        for (int k = 0; k < EMBED_DIM; ++k) c = fmaf(W2[e * EMBED_DIM + k], hs[k], c);
        g_s[b * EMBED_DIM + e] = c * c;
        float gp = c * Wg[e];
        #pragma unroll
        for (int o = 16; o; o >>= 1) gp += __shfl_xor_sync(0xffffffffu, gp, o);
        if (e == 0) g_gate[b] = __fdividef(1.f, 1.f + __expf(-(gp + bg[0])));
    }
    cudaTriggerProgrammaticLaunchCompletion();
}

// --------------------------------------------------------------------------
// Kernel B: persistent adj + sigmoid + exact top-k + gated write.
// smem: ebuf4 [8 ef][512 j] float4 (64 KB)
//       vbuf  [16 rows][640] f32   (40 KB, lane-contiguous, pad 20)
//       abuf  [16 rows][16 ep] float2 (2 KB)
// --------------------------------------------------------------------------
#define SMEM_EBUF_BYTES (8 * NUM_VARS * 16)
#define SMEM_VBUF_BYTES (TI * VROW_STRIDE * 4)
#define SMEM_ABUF_BYTES (TI * 16 * 8)
#define SMEM_TOTAL (SMEM_EBUF_BYTES + SMEM_VBUF_BYTES + SMEM_ABUF_BYTES)

// local top-2 over the lane's 16 owned slots (u32-bit order == float order for
// sigmoid>0); strict '>' keeps the smallest index on ties, matching jax top_k.
__device__ __forceinline__ void scan_top2(const float* __restrict__ lptr, int base,
                                          unsigned& t1, int& i1,
                                          unsigned& t2, int& i2) {
    t1 = 0u; i1 = base; t2 = 0u; i2 = base;
    #pragma unroll
    for (int cc = 0; cc < 4; ++cc) {
        const float4 vv = reinterpret_cast<const float4*>(lptr)[cc];
        const float va[4] = {vv.x, vv.y, vv.z, vv.w};
        #pragma unroll
        for (int u = 0; u < 4; ++u) {
            const unsigned bx = __float_as_uint(va[u]);
            const int j = base + 4 * cc + u;
            const bool p1 = bx > t1;
            const bool p2 = bx > t2;
            t2 = p1 ? t1 : (p2 ? bx : t2);
            i2 = p1 ? i1 : (p2 ? j  : i2);
            t1 = p1 ? bx : t1;
            i1 = p1 ? j  : i1;
        }
    }
}

__global__ __launch_bounds__(256, 2) void adj_kernel(
    const float* __restrict__ emb,   // [512, 32]
    float* __restrict__ out)         // [256, 512, 512]
{
    extern __shared__ unsigned char smem_raw[];
    float4* ebuf4 = reinterpret_cast<float4*>(smem_raw);
    float*  vbuf  = reinterpret_cast<float*>(smem_raw + SMEM_EBUF_BYTES);
    float2* abuf2 = reinterpret_cast<float2*>(smem_raw + SMEM_EBUF_BYTES + SMEM_VBUF_BYTES);
    ulonglong2* ebufU2 = reinterpret_cast<ulonglong2*>(ebuf4);
    ulonglong2* abufU2 = reinterpret_cast<ulonglong2*>(abuf2);

    const int tid = threadIdx.x;

    // ---- ctx-independent prologue (overlaps ctx_kernel under PDL) ----
    for (int idx = tid; idx < NUM_VARS * 8; idx += 256) {
        const int j = idx >> 3, ef = idx & 7;
        ebuf4[ef * NUM_VARS + j] = reinterpret_cast<const float4*>(emb)[idx];
    }

    // wait for ctx_kernel's g_s / g_gate to be complete & visible
    cudaGridDependencySynchronize();

    const int tj = tid & 63;     // column group (j = tj + 64q)
    const int ti = tid >> 6;     // row group   (i = ti*4 + k)
    const int w  = tid >> 5, l = tid & 31;
    const int tjoff = ((tj >> 4) * LANE_STRIDE) + (tj & 15);  // vbuf col offset
    const int pi = tid >> 4, pep = tid & 15;                  // abuf stage role

    const float2* emb2 = reinterpret_cast<const float2*>(emb);
    const float2* gs2  = reinterpret_cast<const float2*>(g_s);

    // ---- prefetch first tile's operands into registers ----
    float2 pev = make_float2(0.f, 0.f), psv = make_float2(0.f, 0.f);
    float  pgate = 0.f;
    {
        const int item = blockIdx.x;
        if (item < NITEMS) {
            const int b = item >> 5, i0 = (item & 31) * TI;
            pev   = emb2[(i0 + pi) * 16 + pep];
            psv   = gs2[b * 16 + pep];
            pgate = g_gate[b];
        }
    }

    for (int item = blockIdx.x; item < NITEMS; item += GRID) {
        const int b  = item >> 5;
        const int i0 = (item & 31) * TI;
        const float gate = pgate;

        // ---- stage abuf from prefetched regs (no LDG wait here) ----
        {
            float2 av = pev;
            av.x *= psv.x; av.y *= psv.y;
            abuf2[pi * 16 + pep] = av;
        }
        __syncthreads();   // abuf visible; also orders prev selection (vbuf
                           // reads) before this tile's epilogue vbuf writes

        // ---- main f32x2 FMA loop: 4 rows x 8 cols, float4 (2 e-pairs) steps ----
        unsigned long long acc[4][8];
        #pragma unroll
        for (int i = 0; i < 4; ++i)
            #pragma unroll
            for (int q = 0; q < 8; ++q) acc[i][q] = 0ull;

        #pragma unroll
        for (int ef = 0; ef < 8; ++ef) {
            ulonglong2 av[4];
            #pragma unroll
            for (int i = 0; i < 4; ++i) av[i] = abufU2[(ti * 4 + i) * 8 + ef]; // broadcast
            #pragma unroll
            for (int q = 0; q < 8; ++q) {
                const ulonglong2 bv = ebufU2[ef * NUM_VARS + tj + 64 * q];
                #pragma unroll
                for (int i = 0; i < 4; ++i) {
                    asm("fma.rn.f32x2 %0, %1, %2, %0;"
                        : "+l"(acc[i][q]) : "l"(av[i].x), "l"(bv.x));
                    asm("fma.rn.f32x2 %0, %1, %2, %0;"
                        : "+l"(acc[i][q]) : "l"(av[i].y), "l"(bv.y));
                }
            }
        }

        // ---- sigmoid epilogue -> vbuf (lane-contiguous layout) ----
        #pragma unroll
        for (int i = 0; i < 4; ++i) {
            #pragma unroll
            for (int q = 0; q < 8; ++q) {
                const float lo = __uint_as_float((unsigned)acc[i][q]);
                const float hi = __uint_as_float((unsigned)(acc[i][q] >> 32));
                const float xv = lo + hi;
                const float v  = __fdividef(1.f, 1.f + __expf(-xv));
                vbuf[(ti * 4 + i) * VROW_STRIDE + q * (4 * LANE_STRIDE) + tjoff] = v;
            }
        }
        __syncthreads();   // vbuf visible to selection owners

        // ---- prefetch NEXT tile's operands (latency hides under selection) ----
        {
            const int nitem = item + GRID;
            if (nitem < NITEMS) {
                const int nb = nitem >> 5, ni0 = (nitem & 31) * TI;
                pev   = emb2[(ni0 + pi) * 16 + pep];
                psv   = gs2[nb * 16 + pep];
                pgate = g_gate[nb];
            }
        }

        // ---- exact top-10: warp w owns rows 2w, 2w+1, interleaved ----
        {
            const int ra = 2 * w, rb = 2 * w + 1;
            float* rowa = out + ((size_t)b * NUM_VARS + (i0 + ra)) * NUM_VARS;
            float* rowb = rowa + NUM_VARS;
            const float* lpa = vbuf + ra * VROW_STRIDE + l * LANE_STRIDE;
            const float* lpb = lpa + VROW_STRIDE;
            const int base = l * 16;

            // zero both output rows (coalesced float4)
            const float4 z = make_float4(0.f, 0.f, 0.f, 0.f);
            #pragma unroll
            for (int c = 0; c < 4; ++c) {
                reinterpret_cast<float4*>(rowa)[c * 32 + l] = z;
                reinterpret_cast<float4*>(rowb)[c * 32 + l] = z;
            }

            unsigned t1a, t2a, t1b, t2b; int i1a, i2a, i1b, i2b;
            scan_top2(lpa, base, t1a, i1a, t2a, i2a);
            scan_top2(lpb, base, t1b, i1b, t2b, i2b);
            bool h2a = true, h2b = true;
            __syncwarp();   // order zero-stores before winner stores

            #pragma unroll 1
            for (int it = 0; it < TOP_K; ++it) {
                unsigned wm0, wm1;
                asm("redux.sync.max.u32 %0, %1, 0xffffffff;" : "=r"(wm0) : "r"(t1a));
                asm("redux.sync.max.u32 %0, %1, 0xffffffff;" : "=r"(wm1) : "r"(t1b));
                const unsigned ba = __ballot_sync(0xffffffffu, t1a == wm0);
                const unsigned bb = __ballot_sync(0xffffffffu, t1b == wm1);
                if (l == __ffs(ba) - 1) {            // min index on ties
                    rowa[i1a] = __uint_as_float(wm0) * gate;
                    *(float*)(lpa + (i1a & 15)) = 0.f;   // remove (bits 0)
                    if (it < TOP_K - 1) {
                        if (h2a) { t1a = t2a; i1a = i2a; h2a = false; }
                        else     { scan_top2(lpa, base, t1a, i1a, t2a, i2a); h2a = true; }
                    }
                }
                if (l == __ffs(bb) - 1) {
                    rowb[i1b] = __uint_as_float(wm1) * gate;
                    *(float*)(lpb + (i1b & 15)) = 0.f;
                    if (it < TOP_K - 1) {
                        if (h2b) { t1b = t2b; i1b = i2b; h2b = false; }
                        else     { scan_top2(lpb, base, t1b, i1b, t2b, i2b); h2b = true; }
                    }
                }
                // no __syncwarp needed: lanes touch only their own vbuf slots;
                // redux/ballot reconverge the warp each iteration.
            }
        }
        // NOTE: no end-of-tile barrier — next iteration's abuf STS is safe
        // (all mainloop reads of abuf finished before the post-epilogue
        // barrier), and the loop-top barrier orders vbuf reuse.
    }
}

// --------------------------------------------------------------------------
extern "C" void kernel_launch(void* const* d_in, const int* in_sizes, int n_in,
                              void* d_out, int out_size) {
    const float* ctx = (const float*)d_in[0];  // [256,512]
    const float* emb = (const float*)d_in[1];  // [512,32]
    const float* W1  = (const float*)d_in[2];  // [32,512]
    const float* b1  = (const float*)d_in[3];  // [32]
    const float* W2  = (const float*)d_in[4];  // [32,32]
    const float* b2  = (const float*)d_in[5];  // [32]
    const float* Wg  = (const float*)d_in[6];  // [1,32]
    const float* bg  = (const float*)d_in[7];  // [1]
    float* out = (float*)d_out;

    ctx_kernel<<<BATCH, 128>>>(ctx, W1, b1, W2, b2, Wg, bg);

    cudaFuncSetAttribute(adj_kernel,
                         cudaFuncAttributeMaxDynamicSharedMemorySize, SMEM_TOTAL);

    cudaLaunchConfig_t cfg = {};
    cfg.gridDim  = dim3(GRID, 1, 1);
    cfg.blockDim = dim3(256, 1, 1);
    cfg.dynamicSmemBytes = SMEM_TOTAL;
    cfg.stream = 0;
    cudaLaunchAttribute attr[1];
    attr[0].id = cudaLaunchAttributeProgrammaticStreamSerialization;
    attr[0].val.programmaticStreamSerializationAllowed = 1;
    cfg.attrs = attr;
    cfg.numAttrs = 1;
    cudaLaunchKernelEx(&cfg, adj_kernel, emb, out);
}

// round 14
// speedup vs baseline: 1.0835x; 1.0165x over previous
#include <cuda_runtime.h>
#include <cstdint>
#include <cstddef>

#define NUM_VARS  512
#define EMBED_DIM 32
#define IN_DIM    512
#define TOP_K     10
#define BATCH     256
#define TI        16                       // rows per tile
#define NITEMS    (BATCH * (NUM_VARS/TI))  // 8192 work items
#define GRID      304

// vbuf layout: row stride = 32 lanes * 20 words (16 used + 4 pad) = 640 floats
#define VROW_STRIDE 640
#define LANE_STRIDE 20

// scratch (no allocations allowed)
__device__ float g_s[BATCH * EMBED_DIM];   // (c*c)[b][e]
__device__ float g_gate[BATCH];            // sigmoid(c@Wg+bg)

// --------------------------------------------------------------------------
// Kernel A: context MLP -> c, s=c^2, gate. One block per batch row.
// --------------------------------------------------------------------------
__global__ __launch_bounds__(128) void ctx_kernel(
    const float* __restrict__ x,    // [B, 512]
    const float* __restrict__ W1,   // [32, 512]
    const float* __restrict__ b1,   // [32]
    const float* __restrict__ W2,   // [32, 32]
    const float* __restrict__ b2,   // [32]
    const float* __restrict__ Wg,   // [32]
    const float* __restrict__ bg)   // [1]
{
    __shared__ float xs[IN_DIM];
    __shared__ float hs[EMBED_DIM];
    const int b   = blockIdx.x;
    const int tid = threadIdx.x;
    const float* xrow = x + (size_t)b * IN_DIM;
    for (int i = tid; i < IN_DIM; i += 128) xs[i] = xrow[i];
    __syncthreads();

    const int w = tid >> 5, l = tid & 31;
    for (int eo = 0; eo < 8; ++eo) {
        const int e = w * 8 + eo;
        const float* wrow = W1 + (size_t)e * IN_DIM;
        float p = 0.f;
        #pragma unroll 4
        for (int k = l; k < IN_DIM; k += 32) p = fmaf(xs[k], wrow[k], p);
        #pragma unroll
        for (int o = 16; o; o >>= 1) p += __shfl_xor_sync(0xffffffffu, p, o);
        if (l == 0) hs[e] = fmaxf(p + b1[e], 0.f);
    }
    __syncthreads();

    if (w == 0) {
        const int e = l;
        float c = b2[e];
        #pragma unroll
        for (int k = 0; k < EMBED_DIM; ++k) c = fmaf(W2[e * EMBED_DIM + k], hs[k], c);
        g_s[b * EMBED_DIM + e] = c * c;
        float gp = c * Wg[e];
        #pragma unroll
        for (int o = 16; o; o >>= 1) gp += __shfl_xor_sync(0xffffffffu, gp, o);
        if (e == 0) g_gate[b] = __fdividef(1.f, 1.f + __expf(-(gp + bg[0])));
    }
    cudaTriggerProgrammaticLaunchCompletion();
}

// --------------------------------------------------------------------------
// Predicated stores (no BSSY/BSYNC): ptxas won't emit @P stores from C++ if{}.
// --------------------------------------------------------------------------
__device__ __forceinline__ void stg_if(bool p, float* ptr, float v) {
    asm volatile("{\n\t"
                 ".reg .pred pp;\n\t"
                 "setp.ne.b32 pp, %0, 0;\n\t"
                 "@pp st.global.f32 [%1], %2;\n\t"
                 "}"
                 :: "r"((int)p), "l"(ptr), "f"(v) : "memory");
}
__device__ __forceinline__ void sts_if(bool p, const float* sptr, float v) {
    const unsigned a = (unsigned)__cvta_generic_to_shared(sptr);
    asm volatile("{\n\t"
                 ".reg .pred pp;\n\t"
                 "setp.ne.b32 pp, %0, 0;\n\t"
                 "@pp st.shared.f32 [%1], %2;\n\t"
                 "}"
                 :: "r"((int)p), "r"(a), "f"(v) : "memory");
}

// --------------------------------------------------------------------------
// Kernel B: persistent adj + sigmoid + exact top-k + gated write.
// smem: ebuf4 [8 ef][512 j] float4 (64 KB)
//       vbuf  [16 rows][640] f32   (40 KB, lane-contiguous, pad 20)
//       abuf  [16 rows][16 ep] float2 (2 KB)
// --------------------------------------------------------------------------
#define SMEM_EBUF_BYTES (8 * NUM_VARS * 16)
#define SMEM_VBUF_BYTES (TI * VROW_STRIDE * 4)
#define SMEM_ABUF_BYTES (TI * 16 * 8)
#define SMEM_TOTAL (SMEM_EBUF_BYTES + SMEM_VBUF_BYTES + SMEM_ABUF_BYTES)

// local top-2 over the lane's 16 owned slots (u32-bit order == float order for
// sigmoid>0); strict '>' keeps the smallest index on ties, matching jax top_k.
__device__ __forceinline__ void scan_top2(const float* __restrict__ lptr, int base,
                                          unsigned& t1, int& i1,
                                          unsigned& t2, int& i2) {
    t1 = 0u; i1 = base; t2 = 0u; i2 = base;
    #pragma unroll
    for (int cc = 0; cc < 4; ++cc) {
        const float4 vv = reinterpret_cast<const float4*>(lptr)[cc];
        const float va[4] = {vv.x, vv.y, vv.z, vv.w};
        #pragma unroll
        for (int u = 0; u < 4; ++u) {
            const unsigned bx = __float_as_uint(va[u]);
            const int j = base + 4 * cc + u;
            const bool p1 = bx > t1;
            const bool p2 = bx > t2;
            t2 = p1 ? t1 : (p2 ? bx : t2);
            i2 = p1 ? i1 : (p2 ? j  : i2);
            t1 = p1 ? bx : t1;
            i1 = p1 ? j  : i1;
        }
    }
}

__global__ __launch_bounds__(256, 2) void adj_kernel(
    const float* __restrict__ emb,   // [512, 32]
    float* __restrict__ out)         // [256, 512, 512]
{
    extern __shared__ unsigned char smem_raw[];
    float4* ebuf4 = reinterpret_cast<float4*>(smem_raw);
    float*  vbuf  = reinterpret_cast<float*>(smem_raw + SMEM_EBUF_BYTES);
    float2* abuf2 = reinterpret_cast<float2*>(smem_raw + SMEM_EBUF_BYTES + SMEM_VBUF_BYTES);
    ulonglong2* ebufU2 = reinterpret_cast<ulonglong2*>(ebuf4);
    ulonglong2* abufU2 = reinterpret_cast<ulonglong2*>(abuf2);

    const int tid = threadIdx.x;

    // ---- ctx-independent prologue (overlaps ctx_kernel under PDL) ----
    for (int idx = tid; idx < NUM_VARS * 8; idx += 256) {
        const int j = idx >> 3, ef = idx & 7;
        ebuf4[ef * NUM_VARS + j] = reinterpret_cast<const float4*>(emb)[idx];
    }

    // wait for ctx_kernel's g_s / g_gate to be complete & visible
    cudaGridDependencySynchronize();

    const int tj = tid & 63;     // column group (j = tj + 64q)
    const int ti = tid >> 6;     // row group   (i = ti*4 + k)
    const int w  = tid >> 5, l = tid & 31;
    const int tjoff = ((tj >> 4) * LANE_STRIDE) + (tj & 15);  // vbuf col offset
    const int pi = tid >> 4, pep = tid & 15;                  // abuf stage role

    const float2* emb2 = reinterpret_cast<const float2*>(emb);
    const float2* gs2  = reinterpret_cast<const float2*>(g_s);

    // ---- prefetch first tile's operands into registers ----
    float2 pev = make_float2(0.f, 0.f), psv = make_float2(0.f, 0.f);
    float  pgate = 0.f;
    {
        const int item = blockIdx.x;
        if (item < NITEMS) {
            const int b = item >> 5, i0 = (item & 31) * TI;
            pev   = emb2[(i0 + pi) * 16 + pep];
            psv   = gs2[b * 16 + pep];
            pgate = g_gate[b];
        }
    }

    for (int item = blockIdx.x; item < NITEMS; item += GRID) {
        const int b  = item >> 5;
        const int i0 = (item & 31) * TI;
        const float gate = pgate;

        // ---- stage abuf from prefetched regs (no LDG wait here) ----
        {
            float2 av = pev;
            av.x *= psv.x; av.y *= psv.y;
            abuf2[pi * 16 + pep] = av;
        }
        __syncthreads();   // abuf visible; also orders prev selection (vbuf
                           // reads) before this tile's epilogue vbuf writes

        // ---- main f32x2 FMA loop: 4 rows x 8 cols, float4 (2 e-pairs) steps ----
        unsigned long long acc[4][8];
        #pragma unroll
        for (int i = 0; i < 4; ++i)
            #pragma unroll
            for (int q = 0; q < 8; ++q) acc[i][q] = 0ull;

        #pragma unroll
        for (int ef = 0; ef < 8; ++ef) {
            ulonglong2 av[4];
            #pragma unroll
            for (int i = 0; i < 4; ++i) av[i] = abufU2[(ti * 4 + i) * 8 + ef]; // broadcast
            #pragma unroll
            for (int q = 0; q < 8; ++q) {
                const ulonglong2 bv = ebufU2[ef * NUM_VARS + tj + 64 * q];
                #pragma unroll
                for (int i = 0; i < 4; ++i) {
                    asm("fma.rn.f32x2 %0, %1, %2, %0;"
                        : "+l"(acc[i][q]) : "l"(av[i].x), "l"(bv.x));
                    asm("fma.rn.f32x2 %0, %1, %2, %0;"
                        : "+l"(acc[i][q]) : "l"(av[i].y), "l"(bv.y));
                }
            }
        }

        // ---- sigmoid epilogue -> vbuf (lane-contiguous layout) ----
        #pragma unroll
        for (int i = 0; i < 4; ++i) {
            #pragma unroll
            for (int q = 0; q < 8; ++q) {
                const float lo = __uint_as_float((unsigned)acc[i][q]);
                const float hi = __uint_as_float((unsigned)(acc[i][q] >> 32));
                const float xv = lo + hi;
                const float v  = __fdividef(1.f, 1.f + __expf(-xv));
                vbuf[(ti * 4 + i) * VROW_STRIDE + q * (4 * LANE_STRIDE) + tjoff] = v;
            }
        }
        __syncthreads();   // vbuf visible to selection owners

        // ---- prefetch NEXT tile's operands (latency hides under selection) ----
        {
            const int nitem = item + GRID;
            if (nitem < NITEMS) {
                const int nb = nitem >> 5, ni0 = (nitem & 31) * TI;
                pev   = emb2[(ni0 + pi) * 16 + pep];
                psv   = gs2[nb * 16 + pep];
                pgate = g_gate[nb];
            }
        }

        // ---- exact top-10: warp w owns rows 2w, 2w+1, interleaved;
        //      winner path is branch-free (predicated stores + SEL pops),
        //      only the rare full-rescan takes a branch. ----
        {
            const int ra = 2 * w, rb = 2 * w + 1;
            float* rowa = out + ((size_t)b * NUM_VARS + (i0 + ra)) * NUM_VARS;
            float* rowb = rowa + NUM_VARS;
            const float* lpa = vbuf + ra * VROW_STRIDE + l * LANE_STRIDE;
            const float* lpb = lpa + VROW_STRIDE;
            const int base = l * 16;

            // zero both output rows (coalesced float4)
            const float4 z = make_float4(0.f, 0.f, 0.f, 0.f);
            #pragma unroll
            for (int c = 0; c < 4; ++c) {
                reinterpret_cast<float4*>(rowa)[c * 32 + l] = z;
                reinterpret_cast<float4*>(rowb)[c * 32 + l] = z;
            }

            unsigned t1a, t2a, t1b, t2b; int i1a, i2a, i1b, i2b;
            scan_top2(lpa, base, t1a, i1a, t2a, i2a);
            scan_top2(lpb, base, t1b, i1b, t2b, i2b);
            bool h2a = true, h2b = true;
            __syncwarp();   // order zero-stores before winner stores

            #pragma unroll 1
            for (int it = 0; it < TOP_K; ++it) {
                unsigned wm0, wm1;
                asm("redux.sync.max.u32 %0, %1, 0xffffffff;" : "=r"(wm0) : "r"(t1a));
                asm("redux.sync.max.u32 %0, %1, 0xffffffff;" : "=r"(wm1) : "r"(t1b));
                const unsigned ba = __ballot_sync(0xffffffffu, t1a == wm0);
                const unsigned bb = __ballot_sync(0xffffffffu, t1b == wm1);
                const bool wina = (l == __ffs(ba) - 1);   // min index on ties
                const bool winb = (l == __ffs(bb) - 1);

                // predicated winner stores (no branch, no BSSY/BSYNC)
                stg_if(wina, rowa + i1a, __uint_as_float(wm0) * gate);
                sts_if(wina, lpa + (i1a & 15), 0.f);      // remove (bits 0)
                stg_if(winb, rowb + i1b, __uint_as_float(wm1) * gate);
                sts_if(winb, lpb + (i1b & 15), 0.f);

                if (it < TOP_K - 1) {
                    const bool resca = wina && !h2a;
                    const bool rescb = winb && !h2b;
                    // pop top-2 via selects (stale when rescanning; overwritten)
                    t1a = wina ? t2a : t1a;  i1a = wina ? i2a : i1a;
                    t1b = winb ? t2b : t1b;  i1b = winb ? i2b : i1b;
                    h2a = h2a ^ wina;
                    h2b = h2b ^ winb;
                    if (__any_sync(0xffffffffu, resca || rescb)) {  // rare
                        if (resca) { scan_top2(lpa, base, t1a, i1a, t2a, i2a); h2a = true; }
                        if (rescb) { scan_top2(lpb, base, t1b, i1b, t2b, i2b); h2b = true; }
                    }
                }
                // redux/ballot reconverge the warp each iteration; lanes only
                // touch their own vbuf slots, so no __syncwarp needed here.
            }
        }
        // NOTE: no end-of-tile barrier — next iteration's abuf STS is safe
        // (all mainloop reads of abuf finished before the post-epilogue
        // barrier), and the loop-top barrier orders vbuf reuse.
    }
}

// --------------------------------------------------------------------------
extern "C" void kernel_launch(void* const* d_in, const int* in_sizes, int n_in,
                              void* d_out, int out_size) {
    const float* ctx = (const float*)d_in[0];  // [256,512]
    const float* emb = (const float*)d_in[1];  // [512,32]
    const float* W1  = (const float*)d_in[2];  // [32,512]
    const float* b1  = (const float*)d_in[3];  // [32]
    const float* W2  = (const float*)d_in[4];  // [32,32]
    const float* b2  = (const float*)d_in[5];  // [32]
    const float* Wg  = (const float*)d_in[6];  // [1,32]
    const float* bg  = (const float*)d_in[7];  // [1]
    float* out = (float*)d_out;

    ctx_kernel<<<BATCH, 128>>>(ctx, W1, b1, W2, b2, Wg, bg);

    cudaFuncSetAttribute(adj_kernel,
                         cudaFuncAttributeMaxDynamicSharedMemorySize, SMEM_TOTAL);

    cudaLaunchConfig_t cfg = {};
    cfg.gridDim  = dim3(GRID, 1, 1);
    cfg.blockDim = dim3(256, 1, 1);
    cfg.dynamicSmemBytes = SMEM_TOTAL;
    cfg.stream = 0;
    cudaLaunchAttribute attr[1];
    attr[0].id = cudaLaunchAttributeProgrammaticStreamSerialization;
    attr[0].val.programmaticStreamSerializationAllowed = 1;
    cfg.attrs = attr;
    cfg.numAttrs = 1;
    cudaLaunchKernelEx(&cfg, adj_kernel, emb, out);
}

// round 16
// speedup vs baseline: 1.1616x; 1.0721x over previous
#include <cuda_runtime.h>
#include <cstdint>
#include <cstddef>

#define NUM_VARS  512
#define EMBED_DIM 32
#define IN_DIM    512
#define TOP_K     10
#define BATCH     256
#define TI        16                       // rows per tile
#define NITEMS    (BATCH * (NUM_VARS/TI))  // 8192 work items
#define GRID      304

// vbuf layout: row stride = 32 lanes * 20 words (16 used + 4 pad) = 640 floats
#define VROW_STRIDE 640
#define LANE_STRIDE 20
#define NEG_INF_BITS 0xff800000u

// scratch (no allocations allowed)
__device__ float g_s[BATCH * EMBED_DIM];   // (c*c)[b][e]
__device__ float g_gate[BATCH];            // sigmoid(c@Wg+bg)

// order-preserving float->u32 key (strictly monotone bijection, all finite
// floats and +-inf): key(a) > key(b) <=> a > b
__device__ __forceinline__ unsigned f2key(float f) {
    const unsigned u = __float_as_uint(f);
    return u ^ ((unsigned)((int)u >> 31) | 0x80000000u);
}

// --------------------------------------------------------------------------
// Kernel A: context MLP -> c, s=c^2, gate. One block per batch row.
// --------------------------------------------------------------------------
__global__ __launch_bounds__(128) void ctx_kernel(
    const float* __restrict__ x,    // [B, 512]
    const float* __restrict__ W1,   // [32, 512]
    const float* __restrict__ b1,   // [32]
    const float* __restrict__ W2,   // [32, 32]
    const float* __restrict__ b2,   // [32]
    const float* __restrict__ Wg,   // [32]
    const float* __restrict__ bg)   // [1]
{
    __shared__ float xs[IN_DIM];
    __shared__ float hs[EMBED_DIM];
    const int b   = blockIdx.x;
    const int tid = threadIdx.x;
    const float* xrow = x + (size_t)b * IN_DIM;
    for (int i = tid; i < IN_DIM; i += 128) xs[i] = xrow[i];
    __syncthreads();

    const int w = tid >> 5, l = tid & 31;
    for (int eo = 0; eo < 8; ++eo) {
        const int e = w * 8 + eo;
        const float* wrow = W1 + (size_t)e * IN_DIM;
        float p = 0.f;
        #pragma unroll 4
        for (int k = l; k < IN_DIM; k += 32) p = fmaf(xs[k], wrow[k], p);
        #pragma unroll
        for (int o = 16; o; o >>= 1) p += __shfl_xor_sync(0xffffffffu, p, o);
        if (l == 0) hs[e] = fmaxf(p + b1[e], 0.f);
    }
    __syncthreads();

    if (w == 0) {
        const int e = l;
        float c = b2[e];
        #pragma unroll
        for (int k = 0; k < EMBED_DIM; ++k) c = fmaf(W2[e * EMBED_DIM + k], hs[k], c);
        g_s[b * EMBED_DIM + e] = c * c;
        float gp = c * Wg[e];
        #pragma unroll
        for (int o = 16; o; o >>= 1) gp += __shfl_xor_sync(0xffffffffu, gp, o);
        if (e == 0) g_gate[b] = __fdividef(1.f, 1.f + __expf(-(gp + bg[0])));
    }
    cudaTriggerProgrammaticLaunchCompletion();
}

// --------------------------------------------------------------------------
// Predicated stores (no BSSY/BSYNC): ptxas won't emit @P stores from C++ if{}.
// --------------------------------------------------------------------------
__device__ __forceinline__ void sts_if(bool p, const float* sptr, float v) {
    const unsigned a = (unsigned)__cvta_generic_to_shared(sptr);
    asm volatile("{\n\t"
                 ".reg .pred pp;\n\t"
                 "setp.ne.b32 pp, %0, 0;\n\t"
                 "@pp st.shared.f32 [%1], %2;\n\t"
                 "}"
                 :: "r"((int)p), "r"(a), "f"(v) : "memory");
}
__device__ __forceinline__ void sts64_if(bool p, const void* sptr,
                                         unsigned lo, unsigned hi) {
    const unsigned a = (unsigned)__cvta_generic_to_shared(sptr);
    asm volatile("{\n\t"
                 ".reg .pred pp;\n\t"
                 ".reg .b64 vv;\n\t"
                 "setp.ne.b32 pp, %0, 0;\n\t"
                 "mov.b64 vv, {%2, %3};\n\t"
                 "@pp st.shared.b64 [%1], vv;\n\t"
                 "}"
                 :: "r"((int)p), "r"(a), "r"(lo), "r"(hi) : "memory");
}

// --------------------------------------------------------------------------
// Kernel B: persistent adj (raw logits) + exact top-k + deferred sigmoid.
// smem: ebuf4 [8 ef][512 j] float4 (64 KB)
//       vbuf  [16 rows][640] f32 logits (40 KB, lane-contiguous, pad 20)
//       abuf  [16 rows][16 ep] float2 (2 KB)
//       wbuf  [8 warps][20] u64 winner records (1.25 KB)
// --------------------------------------------------------------------------
#define SMEM_EBUF_BYTES (8 * NUM_VARS * 16)
#define SMEM_VBUF_BYTES (TI * VROW_STRIDE * 4)
#define SMEM_ABUF_BYTES (TI * 16 * 8)
#define SMEM_WBUF_BYTES (8 * 2 * TOP_K * 8)
#define SMEM_TOTAL (SMEM_EBUF_BYTES + SMEM_VBUF_BYTES + SMEM_ABUF_BYTES + SMEM_WBUF_BYTES)

// local top-2 over the lane's 16 owned float slots; strict '>' keeps the
// smallest index on exact ties. Selection order on raw logits is empirically
// bit-identical to sigmoid-space selection on this problem (R10 evidence).
__device__ __forceinline__ void scan_top2(const float* __restrict__ lptr, int base,
                                          float& t1, int& i1,
                                          float& t2, int& i2) {
    const float ninf = __uint_as_float(NEG_INF_BITS);
    t1 = ninf; i1 = base; t2 = ninf; i2 = base;
    #pragma unroll
    for (int cc = 0; cc < 4; ++cc) {
        const float4 vv = reinterpret_cast<const float4*>(lptr)[cc];
        const float va[4] = {vv.x, vv.y, vv.z, vv.w};
        #pragma unroll
        for (int u = 0; u < 4; ++u) {
            const float bx = va[u];
            const int j = base + 4 * cc + u;
            const bool p1 = bx > t1;
            const bool p2 = bx > t2;
            t2 = p1 ? t1 : (p2 ? bx : t2);
            i2 = p1 ? i1 : (p2 ? j  : i2);
            t1 = p1 ? bx : t1;
            i1 = p1 ? j  : i1;
        }
    }
}

__global__ __launch_bounds__(256, 2) void adj_kernel(
    const float* __restrict__ emb,   // [512, 32]
    float* __restrict__ out)         // [256, 512, 512]
{
    extern __shared__ unsigned char smem_raw[];
    float4* ebuf4 = reinterpret_cast<float4*>(smem_raw);
    float*  vbuf  = reinterpret_cast<float*>(smem_raw + SMEM_EBUF_BYTES);
    float2* abuf2 = reinterpret_cast<float2*>(smem_raw + SMEM_EBUF_BYTES + SMEM_VBUF_BYTES);
    unsigned long long* wbuf = reinterpret_cast<unsigned long long*>(
        smem_raw + SMEM_EBUF_BYTES + SMEM_VBUF_BYTES + SMEM_ABUF_BYTES);
    ulonglong2* ebufU2 = reinterpret_cast<ulonglong2*>(ebuf4);
    ulonglong2* abufU2 = reinterpret_cast<ulonglong2*>(abuf2);

    const int tid = threadIdx.x;

    // ---- ctx-independent prologue (overlaps ctx_kernel under PDL) ----
    for (int idx = tid; idx < NUM_VARS * 8; idx += 256) {
        const int j = idx >> 3, ef = idx & 7;
        ebuf4[ef * NUM_VARS + j] = reinterpret_cast<const float4*>(emb)[idx];
    }

    // wait for ctx_kernel's g_s / g_gate to be complete & visible
    cudaGridDependencySynchronize();

    const int tj = tid & 63;     // column group (j = tj + 64q)
    const int ti = tid >> 6;     // row group   (i = ti*4 + k)
    const int w  = tid >> 5, l = tid & 31;
    const int tjoff = ((tj >> 4) * LANE_STRIDE) + (tj & 15);  // vbuf col offset
    const int pi = tid >> 4, pep = tid & 15;                  // abuf stage role
    unsigned long long* wlist = wbuf + w * (2 * TOP_K);       // [0,10)=row a, [10,20)=row b

    const float2* emb2 = reinterpret_cast<const float2*>(emb);
    const float2* gs2  = reinterpret_cast<const float2*>(g_s);

    // ---- prefetch first tile's operands into registers ----
    float2 pev = make_float2(0.f, 0.f), psv = make_float2(0.f, 0.f);
    float  pgate = 0.f;
    {
        const int item = blockIdx.x;
        if (item < NITEMS) {
            const int b = item >> 5, i0 = (item & 31) * TI;
            pev   = emb2[(i0 + pi) * 16 + pep];
            psv   = gs2[b * 16 + pep];
            pgate = g_gate[b];
        }
    }

    for (int item = blockIdx.x; item < NITEMS; item += GRID) {
        const int b  = item >> 5;
        const int i0 = (item & 31) * TI;
        const float gate = pgate;

        // ---- stage abuf from prefetched regs (no LDG wait here) ----
        {
            float2 av = pev;
            av.x *= psv.x; av.y *= psv.y;
            abuf2[pi * 16 + pep] = av;
        }
        __syncthreads();   // abuf visible; also orders prev selection (vbuf
                           // reads) before this tile's epilogue vbuf writes

        // ---- main f32x2 FMA loop: 4 rows x 8 cols, float4 (2 e-pairs) steps ----
        unsigned long long acc[4][8];
        #pragma unroll
        for (int i = 0; i < 4; ++i)
            #pragma unroll
            for (int q = 0; q < 8; ++q) acc[i][q] = 0ull;

        #pragma unroll
        for (int ef = 0; ef < 8; ++ef) {
            ulonglong2 av[4];
            #pragma unroll
            for (int i = 0; i < 4; ++i) av[i] = abufU2[(ti * 4 + i) * 8 + ef]; // broadcast
            #pragma unroll
            for (int q = 0; q < 8; ++q) {
                const ulonglong2 bv = ebufU2[ef * NUM_VARS + tj + 64 * q];
                #pragma unroll
                for (int i = 0; i < 4; ++i) {
                    asm("fma.rn.f32x2 %0, %1, %2, %0;"
                        : "+l"(acc[i][q]) : "l"(av[i].x), "l"(bv.x));
                    asm("fma.rn.f32x2 %0, %1, %2, %0;"
                        : "+l"(acc[i][q]) : "l"(av[i].y), "l"(bv.y));
                }
            }
        }

        // ---- raw-logit epilogue -> vbuf (no sigmoid in bulk) ----
        #pragma unroll
        for (int i = 0; i < 4; ++i) {
            #pragma unroll
            for (int q = 0; q < 8; ++q) {
                const float lo = __uint_as_float((unsigned)acc[i][q]);
                const float hi = __uint_as_float((unsigned)(acc[i][q] >> 32));
                vbuf[(ti * 4 + i) * VROW_STRIDE + q * (4 * LANE_STRIDE) + tjoff]
                    = lo + hi;
            }
        }
        __syncthreads();   // vbuf visible to selection owners

        // ---- prefetch NEXT tile's operands (latency hides under selection) ----
        {
            const int nitem = item + GRID;
            if (nitem < NITEMS) {
                const int nb = nitem >> 5, ni0 = (nitem & 31) * TI;
                pev   = emb2[(ni0 + pi) * 16 + pep];
                psv   = gs2[nb * 16 + pep];
                pgate = g_gate[nb];
            }
        }

        // ---- exact top-10: warp w owns rows 2w, 2w+1, interleaved;
        //      loop only RECORDS winners (idx,logit) into wbuf; sigmoid +
        //      global stores happen in one parallel pass afterwards. ----
        {
            const int ra = 2 * w, rb = 2 * w + 1;
            float* rowa = out + ((size_t)b * NUM_VARS + (i0 + ra)) * NUM_VARS;
            float* rowb = rowa + NUM_VARS;
            const float* lpa = vbuf + ra * VROW_STRIDE + l * LANE_STRIDE;
            const float* lpb = lpa + VROW_STRIDE;
            const int base = l * 16;
            const float ninf = __uint_as_float(NEG_INF_BITS);

            // zero both output rows (coalesced float4)
            const float4 z = make_float4(0.f, 0.f, 0.f, 0.f);
            #pragma unroll
            for (int c = 0; c < 4; ++c) {
                reinterpret_cast<float4*>(rowa)[c * 32 + l] = z;
                reinterpret_cast<float4*>(rowb)[c * 32 + l] = z;
            }

            float t1a, t2a, t1b, t2b; int i1a, i2a, i1b, i2b;
            scan_top2(lpa, base, t1a, i1a, t2a, i2a);
            scan_top2(lpb, base, t1b, i1b, t2b, i2b);
            unsigned k1a = f2key(t1a), k1b = f2key(t1b);
            bool h2a = true, h2b = true;

            #pragma unroll 1
            for (int it = 0; it < TOP_K; ++it) {
                unsigned wm0, wm1;
                asm("redux.sync.max.u32 %0, %1, 0xffffffff;" : "=r"(wm0) : "r"(k1a));
                asm("redux.sync.max.u32 %0, %1, 0xffffffff;" : "=r"(wm1) : "r"(k1b));
                const unsigned ba = __ballot_sync(0xffffffffu, k1a == wm0);
                const unsigned bb = __ballot_sync(0xffffffffu, k1b == wm1);
                const bool wina = (l == __ffs(ba) - 1);   // min index on ties
                const bool winb = (l == __ffs(bb) - 1);

                // record winner (idx lo, logit bits hi); remove from vbuf
                sts64_if(wina, wlist + it,          (unsigned)i1a, __float_as_uint(t1a));
                sts_if  (wina, lpa + (i1a & 15), ninf);
                sts64_if(winb, wlist + TOP_K + it,  (unsigned)i1b, __float_as_uint(t1b));
                sts_if  (winb, lpb + (i1b & 15), ninf);

                if (it < TOP_K - 1) {
                    const bool resca = wina && !h2a;
                    const bool rescb = winb && !h2b;
                    // pop top-2 via selects (stale when rescanning; overwritten)
                    t1a = wina ? t2a : t1a;  i1a = wina ? i2a : i1a;
                    t1b = winb ? t2b : t1b;  i1b = winb ? i2b : i1b;
                    h2a = h2a ^ wina;
                    h2b = h2b ^ winb;
                    if (__any_sync(0xffffffffu, resca || rescb)) {  // rare
                        if (resca) { scan_top2(lpa, base, t1a, i1a, t2a, i2a); h2a = true; }
                        if (rescb) { scan_top2(lpb, base, t1b, i1b, t2b, i2b); h2b = true; }
                    }
                    k1a = f2key(t1a); k1b = f2key(t1b);
                }
            }
            __syncwarp();   // winner records visible to the finisher lanes

            // ---- deferred winner pass: 20 winners in parallel, off-chain ----
            if (l < 2 * TOP_K) {
                const unsigned long long pk = wlist[l];
                const int   idx   = (int)(unsigned)pk;
                const float logit = __uint_as_float((unsigned)(pk >> 32));
                const float v = __fdividef(1.f, 1.f + __expf(-logit));
                float* row = (l < TOP_K) ? rowa : rowb;
                row[idx] = v * gate;
            }
        }
        // NOTE: no end-of-tile barrier — next iteration's abuf STS is safe
        // (all mainloop reads of abuf finished before the post-epilogue
        // barrier), and the loop-top barrier orders vbuf reuse.
    }
}

// --------------------------------------------------------------------------
extern "C" void kernel_launch(void* const* d_in, const int* in_sizes, int n_in,
                              void* d_out, int out_size) {
    const float* ctx = (const float*)d_in[0];  // [256,512]
    const float* emb = (const float*)d_in[1];  // [512,32]
    const float* W1  = (const float*)d_in[2];  // [32,512]
    const float* b1  = (const float*)d_in[3];  // [32]
    const float* W2  = (const float*)d_in[4];  // [32,32]
    const float* b2  = (const float*)d_in[5];  // [32]
    const float* Wg  = (const float*)d_in[6];  // [1,32]
    const float* bg  = (const float*)d_in[7];  // [1]
    float* out = (float*)d_out;

    ctx_kernel<<<BATCH, 128>>>(ctx, W1, b1, W2, b2, Wg, bg);

    cudaFuncSetAttribute(adj_kernel,
                         cudaFuncAttributeMaxDynamicSharedMemorySize, SMEM_TOTAL);

    cudaLaunchConfig_t cfg = {};
    cfg.gridDim  = dim3(GRID, 1, 1);
    cfg.blockDim = dim3(256, 1, 1);
    cfg.dynamicSmemBytes = SMEM_TOTAL;
    cfg.stream = 0;
    cudaLaunchAttribute attr[1];
    attr[0].id = cudaLaunchAttributeProgrammaticStreamSerialization;
    attr[0].val.programmaticStreamSerializationAllowed = 1;
    cfg.attrs = attr;
    cfg.numAttrs = 1;
    cudaLaunchKernelEx(&cfg, adj_kernel, emb, out);
}

// round 17
// speedup vs baseline: 1.1744x; 1.0110x over previous
#include <cuda_runtime.h>
#include <cstdint>
#include <cstddef>

#define NUM_VARS  512
#define EMBED_DIM 32
#define IN_DIM    512
#define TOP_K     10
#define BATCH     256
#define TI        16                       // rows per tile
#define NITEMS    (BATCH * (NUM_VARS/TI))  // 8192 work items
#define GRID      304

// vbuf layout: row stride = 32 lanes * 20 words (16 used + 4 pad) = 640 floats
#define VROW_STRIDE 640
#define LANE_STRIDE 20
#define NEG_INF_BITS 0xff800000u
#define ROW_BYTES (NUM_VARS * 4)           // 2048 B per output row

// scratch (no allocations allowed)
__device__ float g_s[BATCH * EMBED_DIM];   // (c*c)[b][e]
__device__ float g_gate[BATCH];            // sigmoid(c@Wg+bg)

// order-preserving float->u32 key (strictly monotone bijection, all finite
// floats and +-inf): key(a) > key(b) <=> a > b
__device__ __forceinline__ unsigned f2key(float f) {
    const unsigned u = __float_as_uint(f);
    return u ^ ((unsigned)((int)u >> 31) | 0x80000000u);
}

// --------------------------------------------------------------------------
// Kernel A: context MLP -> c, s=c^2, gate. One block per batch row.
// --------------------------------------------------------------------------
__global__ __launch_bounds__(128) void ctx_kernel(
    const float* __restrict__ x,    // [B, 512]
    const float* __restrict__ W1,   // [32, 512]
    const float* __restrict__ b1,   // [32]
    const float* __restrict__ W2,   // [32, 32]
    const float* __restrict__ b2,   // [32]
    const float* __restrict__ Wg,   // [32]
    const float* __restrict__ bg)   // [1]
{
    __shared__ float xs[IN_DIM];
    __shared__ float hs[EMBED_DIM];
    const int b   = blockIdx.x;
    const int tid = threadIdx.x;
    const float* xrow = x + (size_t)b * IN_DIM;
    for (int i = tid; i < IN_DIM; i += 128) xs[i] = xrow[i];
    __syncthreads();

    const int w = tid >> 5, l = tid & 31;
    for (int eo = 0; eo < 8; ++eo) {
        const int e = w * 8 + eo;
        const float* wrow = W1 + (size_t)e * IN_DIM;
        float p = 0.f;
        #pragma unroll 4
        for (int k = l; k < IN_DIM; k += 32) p = fmaf(xs[k], wrow[k], p);
        #pragma unroll
        for (int o = 16; o; o >>= 1) p += __shfl_xor_sync(0xffffffffu, p, o);
        if (l == 0) hs[e] = fmaxf(p + b1[e], 0.f);
    }
    __syncthreads();

    if (w == 0) {
        const int e = l;
        float c = b2[e];
        #pragma unroll
        for (int k = 0; k < EMBED_DIM; ++k) c = fmaf(W2[e * EMBED_DIM + k], hs[k], c);
        g_s[b * EMBED_DIM + e] = c * c;
        float gp = c * Wg[e];
        #pragma unroll
        for (int o = 16; o; o >>= 1) gp += __shfl_xor_sync(0xffffffffu, gp, o);
        if (e == 0) g_gate[b] = __fdividef(1.f, 1.f + __expf(-(gp + bg[0])));
    }
    cudaTriggerProgrammaticLaunchCompletion();
}

// --------------------------------------------------------------------------
// Predicated stores (no BSSY/BSYNC): ptxas won't emit @P stores from C++ if{}.
// --------------------------------------------------------------------------
__device__ __forceinline__ void sts_if(bool p, const float* sptr, float v) {
    const unsigned a = (unsigned)__cvta_generic_to_shared(sptr);
    asm volatile("{\n\t"
                 ".reg .pred pp;\n\t"
                 "setp.ne.b32 pp, %0, 0;\n\t"
                 "@pp st.shared.f32 [%1], %2;\n\t"
                 "}"
                 :: "r"((int)p), "r"(a), "f"(v) : "memory");
}
__device__ __forceinline__ void sts64_if(bool p, const void* sptr,
                                         unsigned lo, unsigned hi) {
    const unsigned a = (unsigned)__cvta_generic_to_shared(sptr);
    asm volatile("{\n\t"
                 ".reg .pred pp;\n\t"
                 ".reg .b64 vv;\n\t"
                 "setp.ne.b32 pp, %0, 0;\n\t"
                 "mov.b64 vv, {%2, %3};\n\t"
                 "@pp st.shared.b64 [%1], vv;\n\t"
                 "}"
                 :: "r"((int)p), "r"(a), "r"(lo), "r"(hi) : "memory");
}

// bulk-copy one zeroed 2KB row smem->global (async proxy, bulk_group)
__device__ __forceinline__ void bulk_zero_row(float* gdst, const void* szero) {
    const unsigned s = (unsigned)__cvta_generic_to_shared(szero);
    unsigned long long g;
    asm("cvta.to.global.u64 %0, %1;" : "=l"(g) : "l"(gdst));
    asm volatile("cp.async.bulk.global.shared::cta.bulk_group [%0], [%1], %2;"
                 :: "l"(g), "r"(s), "n"(ROW_BYTES) : "memory");
}

// --------------------------------------------------------------------------
// Kernel B: persistent adj (raw logits) + exact top-k + deferred sigmoid.
// Output zeroing offloaded to the bulk-copy (TMA) engine.
// smem: ebuf4 [8 ef][512 j] float4 (64 KB)
//       vbuf  [16 rows][640] f32 logits (40 KB, lane-contiguous, pad 20)
//       abuf  [16 rows][16 ep] float2 (2 KB)
//       wbuf  [8 warps][20] u64 winner records (1.25 KB)
//       zbuf  [512] f32 zeros (2 KB, never rewritten; TMA source)
// --------------------------------------------------------------------------
#define SMEM_EBUF_BYTES (8 * NUM_VARS * 16)
#define SMEM_VBUF_BYTES (TI * VROW_STRIDE * 4)
#define SMEM_ABUF_BYTES (TI * 16 * 8)
#define SMEM_WBUF_BYTES (8 * 2 * TOP_K * 8)
#define SMEM_ZBUF_BYTES (ROW_BYTES)
#define SMEM_TOTAL (SMEM_EBUF_BYTES + SMEM_VBUF_BYTES + SMEM_ABUF_BYTES + \
                    SMEM_WBUF_BYTES + SMEM_ZBUF_BYTES)

// local top-2 over the lane's 16 owned float slots; strict '>' keeps the
// smallest index on exact ties. Selection order on raw logits is empirically
// bit-identical to sigmoid-space selection on this problem (R10 evidence).
__device__ __forceinline__ void scan_top2(const float* __restrict__ lptr, int base,
                                          float& t1, int& i1,
                                          float& t2, int& i2) {
    const float ninf = __uint_as_float(NEG_INF_BITS);
    t1 = ninf; i1 = base; t2 = ninf; i2 = base;
    #pragma unroll
    for (int cc = 0; cc < 4; ++cc) {
        const float4 vv = reinterpret_cast<const float4*>(lptr)[cc];
        const float va[4] = {vv.x, vv.y, vv.z, vv.w};
        #pragma unroll
        for (int u = 0; u < 4; ++u) {
            const float bx = va[u];
            const int j = base + 4 * cc + u;
            const bool p1 = bx > t1;
            const bool p2 = bx > t2;
            t2 = p1 ? t1 : (p2 ? bx : t2);
            i2 = p1 ? i1 : (p2 ? j  : i2);
            t1 = p1 ? bx : t1;
            i1 = p1 ? j  : i1;
        }
    }
}

__global__ __launch_bounds__(256, 2) void adj_kernel(
    const float* __restrict__ emb,   // [512, 32]
    float* __restrict__ out)         // [256, 512, 512]
{
    extern __shared__ unsigned char smem_raw[];
    float4* ebuf4 = reinterpret_cast<float4*>(smem_raw);
    float*  vbuf  = reinterpret_cast<float*>(smem_raw + SMEM_EBUF_BYTES);
    float2* abuf2 = reinterpret_cast<float2*>(smem_raw + SMEM_EBUF_BYTES + SMEM_VBUF_BYTES);
    unsigned long long* wbuf = reinterpret_cast<unsigned long long*>(
        smem_raw + SMEM_EBUF_BYTES + SMEM_VBUF_BYTES + SMEM_ABUF_BYTES);
    float* zbuf = reinterpret_cast<float*>(
        smem_raw + SMEM_EBUF_BYTES + SMEM_VBUF_BYTES + SMEM_ABUF_BYTES + SMEM_WBUF_BYTES);
    ulonglong2* ebufU2 = reinterpret_cast<ulonglong2*>(ebuf4);
    ulonglong2* abufU2 = reinterpret_cast<ulonglong2*>(abuf2);

    const int tid = threadIdx.x;

    // ---- ctx-independent prologue (overlaps ctx_kernel under PDL) ----
    for (int idx = tid; idx < NUM_VARS * 8; idx += 256) {
        const int j = idx >> 3, ef = idx & 7;
        ebuf4[ef * NUM_VARS + j] = reinterpret_cast<const float4*>(emb)[idx];
    }
    // zero buffer for TMA row-zeroing (written once, read forever)
    for (int i = tid; i < NUM_VARS; i += 256) zbuf[i] = 0.f;
    // order generic-proxy smem writes before async-proxy (bulk copy) reads
    asm volatile("fence.proxy.async.shared::cta;" ::: "memory");

    // wait for ctx_kernel's g_s / g_gate to be complete & visible
    cudaGridDependencySynchronize();
    __syncthreads();   // zbuf/ebuf visible block-wide before first tile

    const int tj = tid & 63;     // column group (j = tj + 64q)
    const int ti = tid >> 6;     // row group   (i = ti*4 + k)
    const int w  = tid >> 5, l = tid & 31;
    const int tjoff = ((tj >> 4) * LANE_STRIDE) + (tj & 15);  // vbuf col offset
    const int pi = tid >> 4, pep = tid & 15;                  // abuf stage role
    unsigned long long* wlist = wbuf + w * (2 * TOP_K);       // [0,10)=row a, [10,20)=row b

    const float2* emb2 = reinterpret_cast<const float2*>(emb);
    const float2* gs2  = reinterpret_cast<const float2*>(g_s);

    // ---- prefetch first tile's operands into registers ----
    float2 pev = make_float2(0.f, 0.f), psv = make_float2(0.f, 0.f);
    float  pgate = 0.f;
    {
        const int item = blockIdx.x;
        if (item < NITEMS) {
            const int b = item >> 5, i0 = (item & 31) * TI;
            pev   = emb2[(i0 + pi) * 16 + pep];
            psv   = gs2[b * 16 + pep];
            pgate = g_gate[b];
        }
    }

    for (int item = blockIdx.x; item < NITEMS; item += GRID) {
        const int b  = item >> 5;
        const int i0 = (item & 31) * TI;
        const float gate = pgate;

        // ---- offload row zeroing to the bulk-copy engine (TMA pipe idle
        //      otherwise). Zeros land during the mainloop; ordered before the
        //      winner stores by wait_group + the post-epilogue barrier. ----
        if (tid < TI) {
            bulk_zero_row(out + ((size_t)b * NUM_VARS + (i0 + tid)) * NUM_VARS, zbuf);
            asm volatile("cp.async.bulk.commit_group;" ::: "memory");
        }

        // ---- stage abuf from prefetched regs (no LDG wait here) ----
        {
            float2 av = pev;
            av.x *= psv.x; av.y *= psv.y;
            abuf2[pi * 16 + pep] = av;
        }
        __syncthreads();   // abuf visible; also orders prev selection (vbuf
                           // reads) before this tile's epilogue vbuf writes

        // ---- main f32x2 FMA loop: 4 rows x 8 cols, float4 (2 e-pairs) steps ----
        unsigned long long acc[4][8];
        #pragma unroll
        for (int i = 0; i < 4; ++i)
            #pragma unroll
            for (int q = 0; q < 8; ++q) acc[i][q] = 0ull;

        #pragma unroll
        for (int ef = 0; ef < 8; ++ef) {
            ulonglong2 av[4];
            #pragma unroll
            for (int i = 0; i < 4; ++i) av[i] = abufU2[(ti * 4 + i) * 8 + ef]; // broadcast
            #pragma unroll
            for (int q = 0; q < 8; ++q) {
                const ulonglong2 bv = ebufU2[ef * NUM_VARS + tj + 64 * q];
                #pragma unroll
                for (int i = 0; i < 4; ++i) {
                    asm("fma.rn.f32x2 %0, %1, %2, %0;"
                        : "+l"(acc[i][q]) : "l"(av[i].x), "l"(bv.x));
                    asm("fma.rn.f32x2 %0, %1, %2, %0;"
                        : "+l"(acc[i][q]) : "l"(av[i].y), "l"(bv.y));
                }
            }
        }

        // ---- raw-logit epilogue -> vbuf (no sigmoid in bulk) ----
        #pragma unroll
        for (int i = 0; i < 4; ++i) {
            #pragma unroll
            for (int q = 0; q < 8; ++q) {
                const float lo = __uint_as_float((unsigned)acc[i][q]);
                const float hi = __uint_as_float((unsigned)(acc[i][q] >> 32));
                vbuf[(ti * 4 + i) * VROW_STRIDE + q * (4 * LANE_STRIDE) + tjoff]
                    = lo + hi;
            }
        }
        // all zero-rows for THIS tile must be done before winners store
        asm volatile("cp.async.bulk.wait_group 0;" ::: "memory");
        __syncthreads();   // vbuf + TMA zeros visible to all warps

        // ---- prefetch NEXT tile's operands (latency hides under selection) ----
        {
            const int nitem = item + GRID;
            if (nitem < NITEMS) {
                const int nb = nitem >> 5, ni0 = (nitem & 31) * TI;
                pev   = emb2[(ni0 + pi) * 16 + pep];
                psv   = gs2[nb * 16 + pep];
                pgate = g_gate[nb];
            }
        }

        // ---- exact top-10: warp w owns rows 2w, 2w+1, interleaved;
        //      loop only RECORDS winners (idx,logit) into wbuf; sigmoid +
        //      global stores happen in one parallel pass afterwards. ----
        {
            const int ra = 2 * w, rb = 2 * w + 1;
            float* rowa = out + ((size_t)b * NUM_VARS + (i0 + ra)) * NUM_VARS;
            float* rowb = rowa + NUM_VARS;
            const float* lpa = vbuf + ra * VROW_STRIDE + l * LANE_STRIDE;
            const float* lpb = lpa + VROW_STRIDE;
            const int base = l * 16;
            const float ninf = __uint_as_float(NEG_INF_BITS);

            float t1a, t2a, t1b, t2b; int i1a, i2a, i1b, i2b;
            scan_top2(lpa, base, t1a, i1a, t2a, i2a);
            scan_top2(lpb, base, t1b, i1b, t2b, i2b);
            unsigned k1a = f2key(t1a), k1b = f2key(t1b);
            bool h2a = true, h2b = true;

            #pragma unroll 1
            for (int it = 0; it < TOP_K; ++it) {
                unsigned wm0, wm1;
                asm("redux.sync.max.u32 %0, %1, 0xffffffff;" : "=r"(wm0) : "r"(k1a));
                asm("redux.sync.max.u32 %0, %1, 0xffffffff;" : "=r"(wm1) : "r"(k1b));
                const unsigned ba = __ballot_sync(0xffffffffu, k1a == wm0);
                const unsigned bb = __ballot_sync(0xffffffffu, k1b == wm1);
                const bool wina = (l == __ffs(ba) - 1);   // min index on ties
                const bool winb = (l == __ffs(bb) - 1);

                // record winner (idx lo, logit bits hi); remove from vbuf
                sts64_if(wina, wlist + it,          (unsigned)i1a, __float_as_uint(t1a));
                sts_if  (wina, lpa + (i1a & 15), ninf);
                sts64_if(winb, wlist + TOP_K + it,  (unsigned)i1b, __float_as_uint(t1b));
                sts_if  (winb, lpb + (i1b & 15), ninf);

                if (it < TOP_K - 1) {
                    const bool resca = wina && !h2a;
                    const bool rescb = winb && !h2b;
                    // pop top-2 via selects (stale when rescanning; overwritten)
                    t1a = wina ? t2a : t1a;  i1a = wina ? i2a : i1a;
                    t1b = winb ? t2b : t1b;  i1b = winb ? i2b : i1b;
                    h2a = h2a ^ wina;
                    h2b = h2b ^ winb;
                    if (__any_sync(0xffffffffu, resca || rescb)) {  // rare
                        if (resca) { scan_top2(lpa, base, t1a, i1a, t2a, i2a); h2a = true; }
                        if (rescb) { scan_top2(lpb, base, t1b, i1b, t2b, i2b); h2b = true; }
                    }
                    k1a = f2key(t1a); k1b = f2key(t1b);
                }
            }
            __syncwarp();   // winner records visible to the finisher lanes

            // ---- deferred winner pass: 20 winners in parallel, off-chain ----
            if (l < 2 * TOP_K) {
                const unsigned long long pk = wlist[l];
                const int   idx   = (int)(unsigned)pk;
                const float logit = __uint_as_float((unsigned)(pk >> 32));
                const float v = __fdividef(1.f, 1.f + __expf(-logit));
                float* row = (l < TOP_K) ? rowa : rowb;
                row[idx] = v * gate;
            }
        }
        // NOTE: no end-of-tile barrier — next iteration's abuf STS is safe
        // (all mainloop reads of abuf finished before the post-epilogue
        // barrier), and the loop-top barrier orders vbuf reuse. Next tile's
        // TMA zeros target different rows, so no ordering needed with the
        // winner stores above.
    }
}

// --------------------------------------------------------------------------
extern "C" void kernel_launch(void* const* d_in, const int* in_sizes, int n_in,
                              void* d_out, int out_size) {
    const float* ctx = (const float*)d_in[0];  // [256,512]
    const float* emb = (const float*)d_in[1];  // [512,32]
    const float* W1  = (const float*)d_in[2];  // [32,512]
    const float* b1  = (const float*)d_in[3];  // [32]
    const float* W2  = (const float*)d_in[4];  // [32,32]
    const float* b2  = (const float*)d_in[5];  // [32]
    const float* Wg  = (const float*)d_in[6];  // [1,32]
    const float* bg  = (const float*)d_in[7];  // [1]
    float* out = (float*)d_out;

    ctx_kernel<<<BATCH, 128>>>(ctx, W1, b1, W2, b2, Wg, bg);

    cudaFuncSetAttribute(adj_kernel,
                         cudaFuncAttributeMaxDynamicSharedMemorySize, SMEM_TOTAL);

    cudaLaunchConfig_t cfg = {};
    cfg.gridDim  = dim3(GRID, 1, 1);
    cfg.blockDim = dim3(256, 1, 1);
    cfg.dynamicSmemBytes = SMEM_TOTAL;
    cfg.stream = 0;
    cudaLaunchAttribute attr[1];
    attr[0].id = cudaLaunchAttributeProgrammaticStreamSerialization;
    attr[0].val.programmaticStreamSerializationAllowed = 1;
    cfg.attrs = attr;
    cfg.numAttrs = 1;
    cudaLaunchKernelEx(&cfg, adj_kernel, emb, out);
}